// round 1
// baseline (speedup 1.0000x reference)
#include <cuda_runtime.h>
#include <cuda_bf16.h>
#include <cstdint>

// Problem constants
#define B_  4
#define T_  2048
#define E_  1024
#define H_  16
#define D_  64
#define SCALE 0.125f   // 1/sqrt(64)

// Scratch (allocation-free rule: __device__ globals)
__device__ float g_q[B_ * H_ * T_ * D_];    // [b][h][t][d]
__device__ float g_k[B_ * H_ * T_ * D_];
__device__ float g_v[B_ * H_ * T_ * D_];
__device__ float g_att[B_ * T_ * E_];       // [b][t][h*D+d]  (heads concatenated)

// ---------------------------------------------------------------------------
// Kernel 1: QKV projection.  q[b,h,t,d] = sum_e x[b,t,e] * W[h,e,d]
// Tile: 64(M) x 64(N=D) x 16(K). 256 threads, 4x4 accum per thread.
// grid = (T/64, 3*H, B); blockIdx.y -> which (q/k/v) * H + h
// ---------------------------------------------------------------------------
__global__ __launch_bounds__(256) void gemm_qkv_kernel(
    const float* __restrict__ x,
    const float* __restrict__ Wq,
    const float* __restrict__ Wk,
    const float* __restrict__ Wv)
{
    const int tm    = blockIdx.x;          // tile over T
    const int which = blockIdx.y / H_;     // 0=q,1=k,2=v
    const int h     = blockIdx.y % H_;
    const int b     = blockIdx.z;

    const float* W = (which == 0) ? Wq : (which == 1) ? Wk : Wv;
    W += (size_t)h * E_ * D_;
    float* out = (which == 0) ? g_q : (which == 1) ? g_k : g_v;
    out += (((size_t)b * H_ + h) * T_ + (size_t)tm * 64) * D_;
    const float* A = x + ((size_t)b * T_ + (size_t)tm * 64) * E_;

    __shared__ float As[64][17];   // 64 x 16, padded
    __shared__ float Bs[16][65];   // 16 x 64, padded

    const int tid = threadIdx.x;
    const int tx = tid & 15;       // 0..15 -> N
    const int ty = tid >> 4;       // 0..15 -> M

    float acc[4][4];
#pragma unroll
    for (int i = 0; i < 4; i++)
#pragma unroll
        for (int j = 0; j < 4; j++) acc[i][j] = 0.f;

    for (int k0 = 0; k0 < E_; k0 += 16) {
        // Load A tile (64x16) and B tile (16x64)
#pragma unroll
        for (int i = 0; i < 4; i++) {
            int idx = tid + i * 256;          // 0..1023
            int r = idx >> 4, c = idx & 15;
            As[r][c] = A[r * E_ + k0 + c];
        }
#pragma unroll
        for (int i = 0; i < 4; i++) {
            int idx = tid + i * 256;
            int r = idx >> 6, c = idx & 63;
            Bs[r][c] = W[(k0 + r) * D_ + c];
        }
        __syncthreads();
#pragma unroll
        for (int kk = 0; kk < 16; kk++) {
            float a[4], bb[4];
#pragma unroll
            for (int i = 0; i < 4; i++) a[i] = As[ty * 4 + i][kk];
#pragma unroll
            for (int j = 0; j < 4; j++) bb[j] = Bs[kk][tx * 4 + j];
#pragma unroll
            for (int i = 0; i < 4; i++)
#pragma unroll
                for (int j = 0; j < 4; j++) acc[i][j] = fmaf(a[i], bb[j], acc[i][j]);
        }
        __syncthreads();
    }
#pragma unroll
    for (int i = 0; i < 4; i++)
#pragma unroll
        for (int j = 0; j < 4; j++)
            out[(ty * 4 + i) * D_ + tx * 4 + j] = acc[i][j];
}

// ---------------------------------------------------------------------------
// Kernel 2: flash attention (causal), fp32, online softmax.
// One block = one 64-row query tile of one (b,h). 256 threads, 4x4 per thread.
// Dynamic SMEM layout: Qs(64x65) Ks(64x65) Ss(64x65) Vs(64x64) + stats
// ---------------------------------------------------------------------------
#define FLASH_SMEM_FLOATS (3 * 64 * 65 + 64 * 64 + 64 * 3 + 256)
#define FLASH_SMEM_BYTES  (FLASH_SMEM_FLOATS * 4)

__global__ __launch_bounds__(256) void flash_attn_kernel()
{
    extern __shared__ float sm[];
    float* Qs     = sm;                 // 64*65
    float* Ks     = Qs + 64 * 65;       // 64*65
    float* Ss     = Ks + 64 * 65;       // 64*65 (scores -> probs in place)
    float* Vs     = Ss + 64 * 65;       // 64*64 (read Vs[kk][col]: conflict-free)
    float* m_s    = Vs + 64 * 64;       // 64
    float* l_s    = m_s + 64;           // 64
    float* corr_s = l_s + 64;           // 64
    float* red    = corr_s + 64;        // 64*4

    const int qt  = blockIdx.x;   // query tile 0..31
    const int h   = blockIdx.y;
    const int b   = blockIdx.z;
    const int tid = threadIdx.x;
    const int tx  = tid & 15;
    const int ty  = tid >> 4;

    const float* qptr  = g_q + (((size_t)b * H_ + h) * T_ + (size_t)qt * 64) * D_;
    const float* kbase = g_k + (((size_t)b * H_ + h) * T_) * D_;
    const float* vbase = g_v + (((size_t)b * H_ + h) * T_) * D_;

    // Load Q tile once
#pragma unroll
    for (int i = 0; i < 16; i++) {
        int idx = tid + i * 256;        // 0..4095
        int r = idx >> 6, c = idx & 63;
        Qs[r * 65 + c] = qptr[idx];
    }
    if (tid < 64) { m_s[tid] = -1e30f; l_s[tid] = 0.f; }

    float acc[4][4];
#pragma unroll
    for (int i = 0; i < 4; i++)
#pragma unroll
        for (int j = 0; j < 4; j++) acc[i][j] = 0.f;
    __syncthreads();

    for (int kj = 0; kj <= qt; kj++) {
        const float* kptr = kbase + (size_t)kj * 64 * D_;
        const float* vptr = vbase + (size_t)kj * 64 * D_;
#pragma unroll
        for (int i = 0; i < 16; i++) {
            int idx = tid + i * 256;
            int r = idx >> 6, c = idx & 63;
            Ks[r * 65 + c] = kptr[idx];
            Vs[r * 64 + c] = vptr[idx];
        }
        __syncthreads();

        // S = scale * Q @ K^T  (+ causal mask on diagonal tile)
        float s[4][4];
#pragma unroll
        for (int i = 0; i < 4; i++)
#pragma unroll
            for (int j = 0; j < 4; j++) s[i][j] = 0.f;
#pragma unroll 8
        for (int kk = 0; kk < 64; kk++) {
            float a[4], bb[4];
#pragma unroll
            for (int i = 0; i < 4; i++) a[i] = Qs[(ty * 4 + i) * 65 + kk];
#pragma unroll
            for (int j = 0; j < 4; j++) bb[j] = Ks[(tx * 4 + j) * 65 + kk];
#pragma unroll
            for (int i = 0; i < 4; i++)
#pragma unroll
                for (int j = 0; j < 4; j++) s[i][j] = fmaf(a[i], bb[j], s[i][j]);
        }
        const bool diag = (kj == qt);
#pragma unroll
        for (int i = 0; i < 4; i++) {
            int row = ty * 4 + i;
#pragma unroll
            for (int j = 0; j < 4; j++) {
                int col = tx * 4 + j;
                float v = s[i][j] * SCALE;
                if (diag && col > row) v = -1e30f;
                Ss[row * 65 + col] = v;
            }
        }
        __syncthreads();

        // Row max (4 threads per row, 16 cols each)
        {
            int row = tid >> 2, part = tid & 3;
            float mx = -1e30f;
            const float* sr = Ss + row * 65 + part * 16;
#pragma unroll
            for (int c = 0; c < 16; c++) mx = fmaxf(mx, sr[c]);
            red[row * 4 + part] = mx;
        }
        __syncthreads();
        if (tid < 64) {
            float mx = fmaxf(fmaxf(red[tid * 4], red[tid * 4 + 1]),
                             fmaxf(red[tid * 4 + 2], red[tid * 4 + 3]));
            float m_new = fmaxf(m_s[tid], mx);
            corr_s[tid] = __expf(m_s[tid] - m_new);
            m_s[tid] = m_new;
        }
        __syncthreads();

        // P = exp(S - m_new) in place + row partial sums
        {
            int row = tid >> 2, part = tid & 3;
            float mn = m_s[row];
            float sum = 0.f;
            float* sr = Ss + row * 65 + part * 16;
#pragma unroll
            for (int c = 0; c < 16; c++) {
                float p = __expf(sr[c] - mn);
                sr[c] = p;
                sum += p;
            }
            red[row * 4 + part] = sum;
        }
        __syncthreads();
        if (tid < 64) {
            l_s[tid] = l_s[tid] * corr_s[tid]
                     + red[tid * 4] + red[tid * 4 + 1] + red[tid * 4 + 2] + red[tid * 4 + 3];
        }
        __syncthreads();

        // O = O*corr + P @ V
        float cf[4];
#pragma unroll
        for (int i = 0; i < 4; i++) cf[i] = corr_s[ty * 4 + i];
#pragma unroll
        for (int i = 0; i < 4; i++)
#pragma unroll
            for (int j = 0; j < 4; j++) acc[i][j] *= cf[i];
#pragma unroll 8
        for (int kk = 0; kk < 64; kk++) {
            float p[4], vv[4];
#pragma unroll
            for (int i = 0; i < 4; i++) p[i] = Ss[(ty * 4 + i) * 65 + kk];
#pragma unroll
            for (int j = 0; j < 4; j++) vv[j] = Vs[kk * 64 + tx * 4 + j];
#pragma unroll
            for (int i = 0; i < 4; i++)
#pragma unroll
                for (int j = 0; j < 4; j++) acc[i][j] = fmaf(p[i], vv[j], acc[i][j]);
        }
        __syncthreads();
    }

    // Final normalize and write to concat-heads layout [b][t][h*D + d]
    float* optr = g_att + ((size_t)b * T_ + (size_t)qt * 64) * E_ + (size_t)h * D_;
#pragma unroll
    for (int i = 0; i < 4; i++) {
        int row = ty * 4 + i;
        float linv = 1.f / l_s[row];
#pragma unroll
        for (int j = 0; j < 4; j++)
            optr[row * E_ + tx * 4 + j] = acc[i][j] * linv;
    }
}

// ---------------------------------------------------------------------------
// Kernel 3: output projection.  out[r][n] = sum_c att[r][c] * Wp[n][c] + bp[n]
// M = B*T = 8192, N = E = 1024, K = E = 1024. B accessed transposed.
// ---------------------------------------------------------------------------
__global__ __launch_bounds__(256) void gemm_proj_kernel(
    const float* __restrict__ Wp,
    const float* __restrict__ bp,
    float* __restrict__ out)
{
    const int tm = blockIdx.x;   // 0..127
    const int tn = blockIdx.y;   // 0..15

    __shared__ float As[64][17];
    __shared__ float Bs[16][65];

    const int tid = threadIdx.x;
    const int tx = tid & 15;
    const int ty = tid >> 4;

    const float* A = g_att + (size_t)tm * 64 * E_;

    float acc[4][4];
#pragma unroll
    for (int i = 0; i < 4; i++)
#pragma unroll
        for (int j = 0; j < 4; j++) acc[i][j] = 0.f;

    for (int k0 = 0; k0 < E_; k0 += 16) {
#pragma unroll
        for (int i = 0; i < 4; i++) {
            int idx = tid + i * 256;
            int r = idx >> 4, c = idx & 15;
            As[r][c] = A[r * E_ + k0 + c];
        }
#pragma unroll
        for (int i = 0; i < 4; i++) {
            int idx = tid + i * 256;
            int n = idx >> 4, c = idx & 15;
            Bs[c][n] = Wp[(size_t)(tn * 64 + n) * E_ + k0 + c];
        }
        __syncthreads();
#pragma unroll
        for (int kk = 0; kk < 16; kk++) {
            float a[4], bb[4];
#pragma unroll
            for (int i = 0; i < 4; i++) a[i] = As[ty * 4 + i][kk];
#pragma unroll
            for (int j = 0; j < 4; j++) bb[j] = Bs[kk][tx * 4 + j];
#pragma unroll
            for (int i = 0; i < 4; i++)
#pragma unroll
                for (int j = 0; j < 4; j++) acc[i][j] = fmaf(a[i], bb[j], acc[i][j]);
        }
        __syncthreads();
    }
#pragma unroll
    for (int i = 0; i < 4; i++) {
        int r = tm * 64 + ty * 4 + i;
#pragma unroll
        for (int j = 0; j < 4; j++) {
            int n = tn * 64 + tx * 4 + j;
            out[(size_t)r * E_ + n] = acc[i][j] + bp[n];
        }
    }
}

// ---------------------------------------------------------------------------
extern "C" void kernel_launch(void* const* d_in, const int* in_sizes, int n_in,
                              void* d_out, int out_size)
{
    const float* x  = (const float*)d_in[0];
    const float* Wq = (const float*)d_in[1];
    const float* Wk = (const float*)d_in[2];
    const float* Wv = (const float*)d_in[3];
    const float* Wp = (const float*)d_in[4];
    const float* bp = (const float*)d_in[5];
    float* out = (float*)d_out;

    cudaFuncSetAttribute(flash_attn_kernel,
                         cudaFuncAttributeMaxDynamicSharedMemorySize,
                         FLASH_SMEM_BYTES);

    // 1) QKV projections
    gemm_qkv_kernel<<<dim3(T_ / 64, 3 * H_, B_), 256>>>(x, Wq, Wk, Wv);
    // 2) causal flash attention
    flash_attn_kernel<<<dim3(T_ / 64, H_, B_), 256, FLASH_SMEM_BYTES>>>();
    // 3) output projection + bias
    gemm_proj_kernel<<<dim3((B_ * T_) / 64, E_ / 64), 256>>>(Wp, bp, out);
}

// round 4
// speedup vs baseline: 1.6870x; 1.6870x over previous
#include <cuda_runtime.h>
#include <cuda_bf16.h>
#include <cstdint>

// Problem constants
#define B_  4
#define T_  2048
#define E_  1024
#define H_  16
#define D_  64
#define SCALE 0.125f   // 1/sqrt(64)

#define M_TOTAL (B_ * T_)          // 8192
#define NQKV    (3 * H_ * D_)      // 3072

// ---------------------------------------------------------------------------
// Scratch (__device__ globals: allocation-free rule)
// ---------------------------------------------------------------------------
__device__ float g_q[B_ * H_ * T_ * D_];
__device__ float g_k[B_ * H_ * T_ * D_];
__device__ float g_v[B_ * H_ * T_ * D_];
__device__ float g_att[B_ * T_ * E_];

// bf16 split operands
__device__ __nv_bfloat16 g_xh[M_TOTAL * E_];
__device__ __nv_bfloat16 g_xl[M_TOTAL * E_];
__device__ __nv_bfloat16 g_bqh[NQKV * E_];    // QKV weights, row n=(which,h,d), col e
__device__ __nv_bfloat16 g_bql[NQKV * E_];
__device__ __nv_bfloat16 g_wph[E_ * E_];      // Wp rows n, cols c (K-major already)
__device__ __nv_bfloat16 g_wpl[E_ * E_];
__device__ __nv_bfloat16 g_ath[M_TOTAL * E_];
__device__ __nv_bfloat16 g_atl[M_TOTAL * E_];

// ---------------------------------------------------------------------------
// mma.sync helper (bf16 -> fp32), m16n8k16
// ---------------------------------------------------------------------------
__device__ __forceinline__ void mma16816(float c[4], const uint32_t a[4],
                                         uint32_t b0, uint32_t b1) {
    asm volatile(
        "mma.sync.aligned.m16n8k16.row.col.f32.bf16.bf16.f32 "
        "{%0,%1,%2,%3}, {%4,%5,%6,%7}, {%8,%9}, {%0,%1,%2,%3};"
        : "+f"(c[0]), "+f"(c[1]), "+f"(c[2]), "+f"(c[3])
        : "r"(a[0]), "r"(a[1]), "r"(a[2]), "r"(a[3]), "r"(b0), "r"(b1));
}

// ---------------------------------------------------------------------------
// Conversion kernels
// ---------------------------------------------------------------------------
__global__ __launch_bounds__(256) void conv_split_kernel(
    const float* __restrict__ src, __nv_bfloat16* __restrict__ hi,
    __nv_bfloat16* __restrict__ lo, int n)
{
    int i = blockIdx.x * 256 + threadIdx.x;
    if (i < n) {
        float v = src[i];
        __nv_bfloat16 h = __float2bfloat16(v);
        hi[i] = h;
        lo[i] = __float2bfloat16(v - __bfloat162float(h));
    }
}

// Transpose Wq/Wk/Wv [h][e][d] -> rows n=(which*1024 + h*64 + d), cols e, split bf16
__global__ __launch_bounds__(256) void conv_wqkv_kernel(
    const float* __restrict__ Wq, const float* __restrict__ Wk, const float* __restrict__ Wv)
{
    __shared__ float tile[32][33];
    const int e0 = blockIdx.x * 32;
    const int d0 = blockIdx.y * 32;
    const int z  = blockIdx.z;            // 0..47
    const int which = z / H_, h = z % H_;
    const float* W = (which == 0) ? Wq : (which == 1) ? Wk : Wv;
    W += (size_t)h * E_ * D_;

    const int tx = threadIdx.x & 31, ty = threadIdx.x >> 5;  // 32 x 8
#pragma unroll
    for (int k = 0; k < 4; k++) {
        int e = e0 + ty + k * 8;
        tile[ty + k * 8][tx] = W[(size_t)e * D_ + d0 + tx];
    }
    __syncthreads();
    const int nbase = which * 1024 + h * 64;
#pragma unroll
    for (int k = 0; k < 4; k++) {
        int d = d0 + ty + k * 8;
        float v = tile[tx][ty + k * 8];
        __nv_bfloat16 hh = __float2bfloat16(v);
        size_t o = (size_t)(nbase + d) * E_ + e0 + tx;
        g_bqh[o] = hh;
        g_bql[o] = __float2bfloat16(v - __bfloat162float(hh));
    }
}

// ---------------------------------------------------------------------------
// Split-bf16 GEMM on mma.sync (HMMA).
// Block tile 128(M) x 128(N), K-chunk 32. 8 warps: 2x4 warp grid, 64x32 each.
// A[M][1024] row-major hi/lo; B[N][1024] row-major hi/lo (B col-major for mma).
// mode 0: QKV -> scatter into g_q/g_k/g_v. mode 1: out = A@B^T + bp.
// ---------------------------------------------------------------------------
#define KC  32
#define LDT 40   // padded SMEM row stride in bf16 units (conflict-free for frag LDS)

__global__ __launch_bounds__(256) void gemm_mma_kernel(int mode, const float* __restrict__ bp,
                                                       float* __restrict__ out)
{
    __shared__ __nv_bfloat16 sm[4 * 128 * LDT];  // Ah, Al, Bh, Bl  (40 KB)
    __nv_bfloat16* Ah = sm;
    __nv_bfloat16* Al = sm + 128 * LDT;
    __nv_bfloat16* Bh = sm + 2 * 128 * LDT;
    __nv_bfloat16* Bl = sm + 3 * 128 * LDT;

    const int tid  = threadIdx.x;
    const int wid  = tid >> 5;
    const int lane = tid & 31;
    const int wm = wid >> 2;          // 0..1  -> rows [wm*64, +64)
    const int wn = wid & 3;           // 0..3  -> cols [wn*32, +32)
    const int group = lane >> 2;      // 0..7
    const int tig   = lane & 3;       // 0..3

    const int m0 = blockIdx.x * 128;
    const int n0 = blockIdx.y * 128;

    const __nv_bfloat16 *gAh, *gAl, *gBh, *gBl;
    if (mode == 0) { gAh = g_xh; gAl = g_xl; gBh = g_bqh; gBl = g_bql; }
    else           { gAh = g_ath; gAl = g_atl; gBh = g_wph; gBl = g_wpl; }

    float acc[4][4][4];               // [mi][ni][frag]
#pragma unroll
    for (int mi = 0; mi < 4; mi++)
#pragma unroll
        for (int ni = 0; ni < 4; ni++)
#pragma unroll
            for (int f = 0; f < 4; f++) acc[mi][ni][f] = 0.f;

    for (int e0 = 0; e0 < E_; e0 += KC) {
        // Load A/B tiles (128 x 32 bf16 each, hi+lo): 512 uint4 per buffer.
#pragma unroll
        for (int i = 0; i < 2; i++) {
            int idx = tid + i * 256;              // 0..511
            int r = idx >> 2, q = idx & 3;        // row, 8-bf16 quad
            const uint4 va = *(const uint4*)(gAh + (size_t)(m0 + r) * E_ + e0 + q * 8);
            *(uint4*)(Ah + r * LDT + q * 8) = va;
            const uint4 vb = *(const uint4*)(gAl + (size_t)(m0 + r) * E_ + e0 + q * 8);
            *(uint4*)(Al + r * LDT + q * 8) = vb;
            const uint4 vc = *(const uint4*)(gBh + (size_t)(n0 + r) * E_ + e0 + q * 8);
            *(uint4*)(Bh + r * LDT + q * 8) = vc;
            const uint4 vd = *(const uint4*)(gBl + (size_t)(n0 + r) * E_ + e0 + q * 8);
            *(uint4*)(Bl + r * LDT + q * 8) = vd;
        }
        __syncthreads();

#pragma unroll
        for (int k0 = 0; k0 < KC; k0 += 16) {
            // A fragments for this k-step (hi and lo)
            uint32_t ah[4][4], al[4][4];
#pragma unroll
            for (int mi = 0; mi < 4; mi++) {
                int r = wm * 64 + mi * 16 + group;
                int c = k0 + tig * 2;
                ah[mi][0] = *(const uint32_t*)(Ah + r * LDT + c);
                ah[mi][1] = *(const uint32_t*)(Ah + (r + 8) * LDT + c);
                ah[mi][2] = *(const uint32_t*)(Ah + r * LDT + c + 8);
                ah[mi][3] = *(const uint32_t*)(Ah + (r + 8) * LDT + c + 8);
                al[mi][0] = *(const uint32_t*)(Al + r * LDT + c);
                al[mi][1] = *(const uint32_t*)(Al + (r + 8) * LDT + c);
                al[mi][2] = *(const uint32_t*)(Al + r * LDT + c + 8);
                al[mi][3] = *(const uint32_t*)(Al + (r + 8) * LDT + c + 8);
            }
#pragma unroll
            for (int ni = 0; ni < 4; ni++) {
                int br = wn * 32 + ni * 8 + group;
                int c = k0 + tig * 2;
                uint32_t bh0 = *(const uint32_t*)(Bh + br * LDT + c);
                uint32_t bh1 = *(const uint32_t*)(Bh + br * LDT + c + 8);
                uint32_t bl0 = *(const uint32_t*)(Bl + br * LDT + c);
                uint32_t bl1 = *(const uint32_t*)(Bl + br * LDT + c + 8);
#pragma unroll
                for (int mi = 0; mi < 4; mi++) {
                    mma16816(acc[mi][ni], ah[mi], bh0, bh1);  // hi*hi
                    mma16816(acc[mi][ni], ah[mi], bl0, bl1);  // hi*lo
                    mma16816(acc[mi][ni], al[mi], bh0, bh1);  // lo*hi
                }
            }
        }
        __syncthreads();
    }

    // Epilogue
#pragma unroll
    for (int mi = 0; mi < 4; mi++) {
        int row0 = m0 + wm * 64 + mi * 16 + group;
#pragma unroll
        for (int ni = 0; ni < 4; ni++) {
            int nc = n0 + wn * 32 + ni * 8 + tig * 2;
            if (mode == 0) {
                const int which = nc >> 10;
                const int rem = nc & 1023;
                const int h = rem >> 6, d = rem & 63;
                float* base = (which == 0) ? g_q : (which == 1) ? g_k : g_v;
                {
                    const int b = row0 >> 11, t = row0 & 2047;
                    float2 v = make_float2(acc[mi][ni][0], acc[mi][ni][1]);
                    *(float2*)(base + (((size_t)(b * H_ + h)) * T_ + t) * D_ + d) = v;
                }
                {
                    const int r1 = row0 + 8;
                    const int b = r1 >> 11, t = r1 & 2047;
                    float2 v = make_float2(acc[mi][ni][2], acc[mi][ni][3]);
                    *(float2*)(base + (((size_t)(b * H_ + h)) * T_ + t) * D_ + d) = v;
                }
            } else {
                float2 bias = *(const float2*)(bp + nc);
                float2 v0 = make_float2(acc[mi][ni][0] + bias.x, acc[mi][ni][1] + bias.y);
                float2 v1 = make_float2(acc[mi][ni][2] + bias.x, acc[mi][ni][3] + bias.y);
                *(float2*)(out + (size_t)row0 * E_ + nc) = v0;
                *(float2*)(out + (size_t)(row0 + 8) * E_ + nc) = v1;
            }
        }
    }
}

// ---------------------------------------------------------------------------
// Flash attention (unchanged, R1-proven)
// ---------------------------------------------------------------------------
#define FLASH_SMEM_FLOATS (3 * 64 * 65 + 64 * 64 + 64 * 3 + 256)
#define FLASH_SMEM_BYTES  (FLASH_SMEM_FLOATS * 4)

__global__ __launch_bounds__(256) void flash_attn_kernel()
{
    extern __shared__ float dynsm[];
    float* Qs     = dynsm;
    float* Ks     = Qs + 64 * 65;
    float* Ss     = Ks + 64 * 65;
    float* Vs     = Ss + 64 * 65;
    float* m_s    = Vs + 64 * 64;
    float* l_s    = m_s + 64;
    float* corr_s = l_s + 64;
    float* red    = corr_s + 64;

    const int qt  = blockIdx.x;
    const int h   = blockIdx.y;
    const int b   = blockIdx.z;
    const int tid = threadIdx.x;
    const int tx  = tid & 15;
    const int ty  = tid >> 4;

    const float* qptr  = g_q + (((size_t)b * H_ + h) * T_ + (size_t)qt * 64) * D_;
    const float* kbase = g_k + (((size_t)b * H_ + h) * T_) * D_;
    const float* vbase = g_v + (((size_t)b * H_ + h) * T_) * D_;

#pragma unroll
    for (int i = 0; i < 16; i++) {
        int idx = tid + i * 256;
        int r = idx >> 6, c = idx & 63;
        Qs[r * 65 + c] = qptr[idx];
    }
    if (tid < 64) { m_s[tid] = -1e30f; l_s[tid] = 0.f; }

    float acc[4][4];
#pragma unroll
    for (int i = 0; i < 4; i++)
#pragma unroll
        for (int j = 0; j < 4; j++) acc[i][j] = 0.f;
    __syncthreads();

    for (int kj = 0; kj <= qt; kj++) {
        const float* kptr = kbase + (size_t)kj * 64 * D_;
        const float* vptr = vbase + (size_t)kj * 64 * D_;
#pragma unroll
        for (int i = 0; i < 16; i++) {
            int idx = tid + i * 256;
            int r = idx >> 6, c = idx & 63;
            Ks[r * 65 + c] = kptr[idx];
            Vs[r * 64 + c] = vptr[idx];
        }
        __syncthreads();

        float s[4][4];
#pragma unroll
        for (int i = 0; i < 4; i++)
#pragma unroll
            for (int j = 0; j < 4; j++) s[i][j] = 0.f;
#pragma unroll 8
        for (int kk = 0; kk < 64; kk++) {
            float a[4], bb[4];
#pragma unroll
            for (int i = 0; i < 4; i++) a[i] = Qs[(ty * 4 + i) * 65 + kk];
#pragma unroll
            for (int j = 0; j < 4; j++) bb[j] = Ks[(tx * 4 + j) * 65 + kk];
#pragma unroll
            for (int i = 0; i < 4; i++)
#pragma unroll
                for (int j = 0; j < 4; j++) s[i][j] = fmaf(a[i], bb[j], s[i][j]);
        }
        const bool diag = (kj == qt);
#pragma unroll
        for (int i = 0; i < 4; i++) {
            int row = ty * 4 + i;
#pragma unroll
            for (int j = 0; j < 4; j++) {
                int col = tx * 4 + j;
                float v = s[i][j] * SCALE;
                if (diag && col > row) v = -1e30f;
                Ss[row * 65 + col] = v;
            }
        }
        __syncthreads();

        {
            int row = tid >> 2, part = tid & 3;
            float mx = -1e30f;
            const float* sr = Ss + row * 65 + part * 16;
#pragma unroll
            for (int c = 0; c < 16; c++) mx = fmaxf(mx, sr[c]);
            red[row * 4 + part] = mx;
        }
        __syncthreads();
        if (tid < 64) {
            float mx = fmaxf(fmaxf(red[tid * 4], red[tid * 4 + 1]),
                             fmaxf(red[tid * 4 + 2], red[tid * 4 + 3]));
            float m_new = fmaxf(m_s[tid], mx);
            corr_s[tid] = __expf(m_s[tid] - m_new);
            m_s[tid] = m_new;
        }
        __syncthreads();

        {
            int row = tid >> 2, part = tid & 3;
            float mn = m_s[row];
            float sum = 0.f;
            float* sr = Ss + row * 65 + part * 16;
#pragma unroll
            for (int c = 0; c < 16; c++) {
                float p = __expf(sr[c] - mn);
                sr[c] = p;
                sum += p;
            }
            red[row * 4 + part] = sum;
        }
        __syncthreads();
        if (tid < 64) {
            l_s[tid] = l_s[tid] * corr_s[tid]
                     + red[tid * 4] + red[tid * 4 + 1] + red[tid * 4 + 2] + red[tid * 4 + 3];
        }
        __syncthreads();

        float cf[4];
#pragma unroll
        for (int i = 0; i < 4; i++) cf[i] = corr_s[ty * 4 + i];
#pragma unroll
        for (int i = 0; i < 4; i++)
#pragma unroll
            for (int j = 0; j < 4; j++) acc[i][j] *= cf[i];
#pragma unroll 8
        for (int kk = 0; kk < 64; kk++) {
            float p[4], vv[4];
#pragma unroll
            for (int i = 0; i < 4; i++) p[i] = Ss[(ty * 4 + i) * 65 + kk];
#pragma unroll
            for (int j = 0; j < 4; j++) vv[j] = Vs[kk * 64 + tx * 4 + j];
#pragma unroll
            for (int i = 0; i < 4; i++)
#pragma unroll
                for (int j = 0; j < 4; j++) acc[i][j] = fmaf(p[i], vv[j], acc[i][j]);
        }
        __syncthreads();
    }

    float* optr = g_att + ((size_t)b * T_ + (size_t)qt * 64) * E_ + (size_t)h * D_;
#pragma unroll
    for (int i = 0; i < 4; i++) {
        int row = ty * 4 + i;
        float linv = 1.f / l_s[row];
#pragma unroll
        for (int j = 0; j < 4; j++)
            optr[row * E_ + tx * 4 + j] = acc[i][j] * linv;
    }
}

// ---------------------------------------------------------------------------
extern "C" void kernel_launch(void* const* d_in, const int* in_sizes, int n_in,
                              void* d_out, int out_size)
{
    const float* x  = (const float*)d_in[0];
    const float* Wq = (const float*)d_in[1];
    const float* Wk = (const float*)d_in[2];
    const float* Wv = (const float*)d_in[3];
    const float* Wp = (const float*)d_in[4];
    const float* bp = (const float*)d_in[5];
    float* out = (float*)d_out;

    cudaFuncSetAttribute(flash_attn_kernel,
                         cudaFuncAttributeMaxDynamicSharedMemorySize, FLASH_SMEM_BYTES);

    __nv_bfloat16 *xh, *xl, *ath, *atl, *wph, *wpl;
    cudaGetSymbolAddress((void**)&xh,  g_xh);
    cudaGetSymbolAddress((void**)&xl,  g_xl);
    cudaGetSymbolAddress((void**)&ath, g_ath);
    cudaGetSymbolAddress((void**)&atl, g_atl);
    cudaGetSymbolAddress((void**)&wph, g_wph);
    cudaGetSymbolAddress((void**)&wpl, g_wpl);
    float* attf;
    cudaGetSymbolAddress((void**)&attf, g_att);

    // 1) split-convert x and weights
    conv_split_kernel<<<(M_TOTAL * E_) / 256, 256>>>(x, xh, xl, M_TOTAL * E_);
    conv_wqkv_kernel<<<dim3(E_ / 32, D_ / 32, 3 * H_), 256>>>(Wq, Wk, Wv);
    conv_split_kernel<<<(E_ * E_) / 256, 256>>>(Wp, wph, wpl, E_ * E_);

    // 2) QKV projection (tensor cores via mma.sync)
    gemm_mma_kernel<<<dim3(M_TOTAL / 128, NQKV / 128), 256>>>(0, nullptr, nullptr);

    // 3) causal flash attention (SIMT fp32)
    flash_attn_kernel<<<dim3(T_ / 64, H_, B_), 256, FLASH_SMEM_BYTES>>>();

    // 4) split-convert attention output, then output projection
    conv_split_kernel<<<(M_TOTAL * E_) / 256, 256>>>(attf, ath, atl, M_TOTAL * E_);
    gemm_mma_kernel<<<dim3(M_TOTAL / 128, E_ / 128), 256>>>(1, bp, out);
}

// round 5
// speedup vs baseline: 2.5769x; 1.5275x over previous
#include <cuda_runtime.h>
#include <cuda_bf16.h>
#include <cstdint>

// Problem constants
#define B_  4
#define T_  2048
#define E_  1024
#define H_  16
#define D_  64

#define M_TOTAL (B_ * T_)          // 8192
#define NQKV    (3 * H_ * D_)      // 3072

// ---------------------------------------------------------------------------
// Scratch (__device__ globals: allocation-free rule)
// ---------------------------------------------------------------------------
// split bf16 Q/K/V: [b][h][t][d]  (Q pre-scaled by 0.125)
__device__ __nv_bfloat16 g_qh[B_ * H_ * T_ * D_];
__device__ __nv_bfloat16 g_ql[B_ * H_ * T_ * D_];
__device__ __nv_bfloat16 g_kh[B_ * H_ * T_ * D_];
__device__ __nv_bfloat16 g_kl[B_ * H_ * T_ * D_];
__device__ __nv_bfloat16 g_vh[B_ * H_ * T_ * D_];
__device__ __nv_bfloat16 g_vl[B_ * H_ * T_ * D_];

// bf16 split GEMM operands
__device__ __nv_bfloat16 g_xh[M_TOTAL * E_];
__device__ __nv_bfloat16 g_xl[M_TOTAL * E_];
__device__ __nv_bfloat16 g_bqh[NQKV * E_];    // QKV weights, row n=(which,h,d), col e
__device__ __nv_bfloat16 g_bql[NQKV * E_];
__device__ __nv_bfloat16 g_wph[E_ * E_];      // Wp rows n, cols c
__device__ __nv_bfloat16 g_wpl[E_ * E_];
__device__ __nv_bfloat16 g_ath[M_TOTAL * E_]; // attention output (written by flash)
__device__ __nv_bfloat16 g_atl[M_TOTAL * E_];

// ---------------------------------------------------------------------------
// Helpers
// ---------------------------------------------------------------------------
__device__ __forceinline__ void mma16816(float c[4], const uint32_t a[4],
                                         uint32_t b0, uint32_t b1) {
    asm volatile(
        "mma.sync.aligned.m16n8k16.row.col.f32.bf16.bf16.f32 "
        "{%0,%1,%2,%3}, {%4,%5,%6,%7}, {%8,%9}, {%0,%1,%2,%3};"
        : "+f"(c[0]), "+f"(c[1]), "+f"(c[2]), "+f"(c[3])
        : "r"(a[0]), "r"(a[1]), "r"(a[2]), "r"(a[3]), "r"(b0), "r"(b1));
}

// pack two fp32 -> bf16x2 (lo in bits [0:16), hi in [16:32))
__device__ __forceinline__ uint32_t pack_bf16x2(float lo, float hi) {
    uint32_t r;
    asm("cvt.rn.bf16x2.f32 %0, %1, %2;" : "=r"(r) : "f"(hi), "f"(lo));
    return r;
}
// split two fp32 into (hi-pair, lo-pair) bf16x2
__device__ __forceinline__ void split2(float v0, float v1, uint32_t& hp, uint32_t& lp) {
    hp = pack_bf16x2(v0, v1);
    float h0 = __uint_as_float(hp << 16);
    float h1 = __uint_as_float(hp & 0xFFFF0000u);
    lp = pack_bf16x2(v0 - h0, v1 - h1);
}

// ---------------------------------------------------------------------------
// Conversion kernels
// ---------------------------------------------------------------------------
__global__ __launch_bounds__(256) void conv_split_kernel(
    const float* __restrict__ src, __nv_bfloat16* __restrict__ hi,
    __nv_bfloat16* __restrict__ lo, int n)
{
    int i = blockIdx.x * 256 + threadIdx.x;
    if (i < n) {
        float v = src[i];
        __nv_bfloat16 h = __float2bfloat16(v);
        hi[i] = h;
        lo[i] = __float2bfloat16(v - __bfloat162float(h));
    }
}

// Transpose Wq/Wk/Wv [h][e][d] -> rows n=(which*1024 + h*64 + d), cols e, split bf16
__global__ __launch_bounds__(256) void conv_wqkv_kernel(
    const float* __restrict__ Wq, const float* __restrict__ Wk, const float* __restrict__ Wv)
{
    __shared__ float tile[32][33];
    const int e0 = blockIdx.x * 32;
    const int d0 = blockIdx.y * 32;
    const int z  = blockIdx.z;            // 0..47
    const int which = z / H_, h = z % H_;
    const float* W = (which == 0) ? Wq : (which == 1) ? Wk : Wv;
    W += (size_t)h * E_ * D_;

    const int tx = threadIdx.x & 31, ty = threadIdx.x >> 5;  // 32 x 8
#pragma unroll
    for (int k = 0; k < 4; k++) {
        int e = e0 + ty + k * 8;
        tile[ty + k * 8][tx] = W[(size_t)e * D_ + d0 + tx];
    }
    __syncthreads();
    const int nbase = which * 1024 + h * 64;
#pragma unroll
    for (int k = 0; k < 4; k++) {
        int d = d0 + ty + k * 8;
        float v = tile[tx][ty + k * 8];
        __nv_bfloat16 hh = __float2bfloat16(v);
        size_t o = (size_t)(nbase + d) * E_ + e0 + tx;
        g_bqh[o] = hh;
        g_bql[o] = __float2bfloat16(v - __bfloat162float(hh));
    }
}

// ---------------------------------------------------------------------------
// Split-bf16 GEMM on mma.sync (HMMA).
// Block tile 128(M) x 128(N), K-chunk 32. 8 warps: 2x4 warp grid, 64x32 each.
// mode 0: QKV -> write split-bf16 q/k/v (Q scaled by 0.125). mode 1: out = A@B^T + bp.
// ---------------------------------------------------------------------------
#define KC  32
#define LDT 40   // padded SMEM row stride in bf16 units

__global__ __launch_bounds__(256) void gemm_mma_kernel(int mode, const float* __restrict__ bp,
                                                       float* __restrict__ out)
{
    __shared__ __nv_bfloat16 sm[4 * 128 * LDT];  // Ah, Al, Bh, Bl  (40 KB)
    __nv_bfloat16* Ah = sm;
    __nv_bfloat16* Al = sm + 128 * LDT;
    __nv_bfloat16* Bh = sm + 2 * 128 * LDT;
    __nv_bfloat16* Bl = sm + 3 * 128 * LDT;

    const int tid  = threadIdx.x;
    const int wid  = tid >> 5;
    const int lane = tid & 31;
    const int wm = wid >> 2;          // 0..1
    const int wn = wid & 3;           // 0..3
    const int group = lane >> 2;      // 0..7
    const int tig   = lane & 3;       // 0..3

    const int m0 = blockIdx.x * 128;
    const int n0 = blockIdx.y * 128;

    const __nv_bfloat16 *gAh, *gAl, *gBh, *gBl;
    if (mode == 0) { gAh = g_xh; gAl = g_xl; gBh = g_bqh; gBl = g_bql; }
    else           { gAh = g_ath; gAl = g_atl; gBh = g_wph; gBl = g_wpl; }

    float acc[4][4][4];
#pragma unroll
    for (int mi = 0; mi < 4; mi++)
#pragma unroll
        for (int ni = 0; ni < 4; ni++)
#pragma unroll
            for (int f = 0; f < 4; f++) acc[mi][ni][f] = 0.f;

    for (int e0 = 0; e0 < E_; e0 += KC) {
#pragma unroll
        for (int i = 0; i < 2; i++) {
            int idx = tid + i * 256;              // 0..511
            int r = idx >> 2, q = idx & 3;
            *(uint4*)(Ah + r * LDT + q * 8) = *(const uint4*)(gAh + (size_t)(m0 + r) * E_ + e0 + q * 8);
            *(uint4*)(Al + r * LDT + q * 8) = *(const uint4*)(gAl + (size_t)(m0 + r) * E_ + e0 + q * 8);
            *(uint4*)(Bh + r * LDT + q * 8) = *(const uint4*)(gBh + (size_t)(n0 + r) * E_ + e0 + q * 8);
            *(uint4*)(Bl + r * LDT + q * 8) = *(const uint4*)(gBl + (size_t)(n0 + r) * E_ + e0 + q * 8);
        }
        __syncthreads();

#pragma unroll
        for (int k0 = 0; k0 < KC; k0 += 16) {
            uint32_t ah[4][4], al[4][4];
#pragma unroll
            for (int mi = 0; mi < 4; mi++) {
                int r = wm * 64 + mi * 16 + group;
                int c = k0 + tig * 2;
                ah[mi][0] = *(const uint32_t*)(Ah + r * LDT + c);
                ah[mi][1] = *(const uint32_t*)(Ah + (r + 8) * LDT + c);
                ah[mi][2] = *(const uint32_t*)(Ah + r * LDT + c + 8);
                ah[mi][3] = *(const uint32_t*)(Ah + (r + 8) * LDT + c + 8);
                al[mi][0] = *(const uint32_t*)(Al + r * LDT + c);
                al[mi][1] = *(const uint32_t*)(Al + (r + 8) * LDT + c);
                al[mi][2] = *(const uint32_t*)(Al + r * LDT + c + 8);
                al[mi][3] = *(const uint32_t*)(Al + (r + 8) * LDT + c + 8);
            }
#pragma unroll
            for (int ni = 0; ni < 4; ni++) {
                int br = wn * 32 + ni * 8 + group;
                int c = k0 + tig * 2;
                uint32_t bh0 = *(const uint32_t*)(Bh + br * LDT + c);
                uint32_t bh1 = *(const uint32_t*)(Bh + br * LDT + c + 8);
                uint32_t bl0 = *(const uint32_t*)(Bl + br * LDT + c);
                uint32_t bl1 = *(const uint32_t*)(Bl + br * LDT + c + 8);
#pragma unroll
                for (int mi = 0; mi < 4; mi++) {
                    mma16816(acc[mi][ni], ah[mi], bh0, bh1);
                    mma16816(acc[mi][ni], ah[mi], bl0, bl1);
                    mma16816(acc[mi][ni], al[mi], bh0, bh1);
                }
            }
        }
        __syncthreads();
    }

    // Epilogue
#pragma unroll
    for (int mi = 0; mi < 4; mi++) {
        int row0 = m0 + wm * 64 + mi * 16 + group;
#pragma unroll
        for (int ni = 0; ni < 4; ni++) {
            int nc = n0 + wn * 32 + ni * 8 + tig * 2;
            if (mode == 0) {
                const int which = nc >> 10;
                const int rem = nc & 1023;
                const int h = rem >> 6, d = rem & 63;
                __nv_bfloat16* bash = (which == 0) ? g_qh : (which == 1) ? g_kh : g_vh;
                __nv_bfloat16* basl = (which == 0) ? g_ql : (which == 1) ? g_kl : g_vl;
                const float sc = (which == 0) ? 0.125f : 1.0f;
#pragma unroll
                for (int half = 0; half < 2; half++) {
                    const int row = row0 + half * 8;
                    const int b = row >> 11, t = row & 2047;
                    float v0 = acc[mi][ni][half * 2] * sc;
                    float v1 = acc[mi][ni][half * 2 + 1] * sc;
                    uint32_t hp, lp;
                    split2(v0, v1, hp, lp);
                    size_t off = (((size_t)(b * H_ + h)) * T_ + t) * D_ + d;
                    *(uint32_t*)(bash + off) = hp;
                    *(uint32_t*)(basl + off) = lp;
                }
            } else {
                float2 bias = *(const float2*)(bp + nc);
                float2 v0 = make_float2(acc[mi][ni][0] + bias.x, acc[mi][ni][1] + bias.y);
                float2 v1 = make_float2(acc[mi][ni][2] + bias.x, acc[mi][ni][3] + bias.y);
                *(float2*)(out + (size_t)row0 * E_ + nc) = v0;
                *(float2*)(out + (size_t)(row0 + 8) * E_ + nc) = v1;
            }
        }
    }
}

// ---------------------------------------------------------------------------
// Flash attention on mma.sync, split-bf16, online softmax in registers.
// CTA: 128 q-rows of one (b,h); 8 warps x 16 rows. kv tiles of 64.
// ---------------------------------------------------------------------------
#define LDK 72   // K smem row stride (bf16 units)

__global__ __launch_bounds__(256) void flash_mma_kernel()
{
    __shared__ __nv_bfloat16 Kh[64 * LDK];
    __shared__ __nv_bfloat16 Kl[64 * LDK];
    __shared__ uint32_t Vhl[64 * 64];   // packed (hi | lo<<16), word (d, kv^((d&3)<<3))

    const int tid  = threadIdx.x;
    const int wid  = tid >> 5;
    const int lane = tid & 31;
    const int g  = lane >> 2;         // 0..7
    const int tg = lane & 3;          // 0..3

    const int qt = blockIdx.x;        // 0..15
    const int h  = blockIdx.y;
    const int b  = blockIdx.z;
    const int bh = b * H_ + h;
    const int q0 = qt * 128;
    const int row_lo = q0 + wid * 16 + g;

    const __nv_bfloat16* gQh = g_qh + (size_t)bh * T_ * D_;
    const __nv_bfloat16* gQl = g_ql + (size_t)bh * T_ * D_;
    const __nv_bfloat16* gKh = g_kh + (size_t)bh * T_ * D_;
    const __nv_bfloat16* gKl = g_kl + (size_t)bh * T_ * D_;
    const __nv_bfloat16* gVh = g_vh + (size_t)bh * T_ * D_;
    const __nv_bfloat16* gVl = g_vl + (size_t)bh * T_ * D_;

    // Preload Q fragments (Q already scaled by 1/sqrt(D))
    uint32_t qh[4][4], ql[4][4];
#pragma unroll
    for (int ks = 0; ks < 4; ks++) {
        int c = ks * 16 + tg * 2;
        qh[ks][0] = *(const uint32_t*)(gQh + (size_t)row_lo * D_ + c);
        qh[ks][1] = *(const uint32_t*)(gQh + (size_t)(row_lo + 8) * D_ + c);
        qh[ks][2] = *(const uint32_t*)(gQh + (size_t)row_lo * D_ + c + 8);
        qh[ks][3] = *(const uint32_t*)(gQh + (size_t)(row_lo + 8) * D_ + c + 8);
        ql[ks][0] = *(const uint32_t*)(gQl + (size_t)row_lo * D_ + c);
        ql[ks][1] = *(const uint32_t*)(gQl + (size_t)(row_lo + 8) * D_ + c);
        ql[ks][2] = *(const uint32_t*)(gQl + (size_t)row_lo * D_ + c + 8);
        ql[ks][3] = *(const uint32_t*)(gQl + (size_t)(row_lo + 8) * D_ + c + 8);
    }

    float m0 = -1e30f, m1 = -1e30f, l0 = 0.f, l1 = 0.f;
    float o[8][4];
#pragma unroll
    for (int nd = 0; nd < 8; nd++)
#pragma unroll
        for (int f = 0; f < 4; f++) o[nd][f] = 0.f;

    const int ntiles = 2 * qt + 2;
    for (int j = 0; j < ntiles; j++) {
        const int kv0 = j * 64;
        // ---- load K tile (64 x 64 bf16, hi+lo) ----
#pragma unroll
        for (int i = 0; i < 2; i++) {
            int idx = tid + i * 256;        // 0..511
            int r = idx >> 3, qd = idx & 7;
            *(uint4*)(Kh + r * LDK + qd * 8) =
                *(const uint4*)(gKh + (size_t)(kv0 + r) * D_ + qd * 8);
            *(uint4*)(Kl + r * LDK + qd * 8) =
                *(const uint4*)(gKl + (size_t)(kv0 + r) * D_ + qd * 8);
        }
        // ---- load V tile transposed+packed: Vhl[d][kv] = hi | lo<<16 ----
#pragma unroll
        for (int i = 0; i < 2; i++) {
            int idx = tid + i * 256;        // 0..511
            int kv = idx & 63, dq = idx >> 6;   // dq 0..7
            uint4 vh = *(const uint4*)(gVh + (size_t)(kv0 + kv) * D_ + dq * 8);
            uint4 vl = *(const uint4*)(gVl + (size_t)(kv0 + kv) * D_ + dq * 8);
            const uint32_t* vhw = (const uint32_t*)&vh;
            const uint32_t* vlw = (const uint32_t*)&vl;
#pragma unroll
            for (int jj = 0; jj < 8; jj++) {
                uint32_t hv = vhw[jj >> 1], lv = vlw[jj >> 1];
                uint32_t packed = __byte_perm(hv, lv, (jj & 1) ? 0x7632 : 0x5410);
                int d = dq * 8 + jj;
                Vhl[d * 64 + (kv ^ ((jj & 3) << 3))] = packed;
            }
        }
        __syncthreads();

        // ---- S = Q K^T (split 3-MMA) ----
        float s[8][4];
#pragma unroll
        for (int nf = 0; nf < 8; nf++)
#pragma unroll
            for (int f = 0; f < 4; f++) s[nf][f] = 0.f;
#pragma unroll
        for (int ks = 0; ks < 4; ks++) {
            int c = ks * 16 + tg * 2;
#pragma unroll
            for (int nf = 0; nf < 8; nf++) {
                int br = nf * 8 + g;
                uint32_t bh0 = *(const uint32_t*)(Kh + br * LDK + c);
                uint32_t bh1 = *(const uint32_t*)(Kh + br * LDK + c + 8);
                uint32_t bl0 = *(const uint32_t*)(Kl + br * LDK + c);
                uint32_t bl1 = *(const uint32_t*)(Kl + br * LDK + c + 8);
                mma16816(s[nf], qh[ks], bh0, bh1);
                mma16816(s[nf], qh[ks], bl0, bl1);
                mma16816(s[nf], ql[ks], bh0, bh1);
            }
        }

        // ---- causal mask (only last two tiles can touch diagonal) ----
        if (j >= ntiles - 2) {
#pragma unroll
            for (int nf = 0; nf < 8; nf++) {
                int col = kv0 + nf * 8 + tg * 2;
                if (col > row_lo)     s[nf][0] = -1e30f;
                if (col + 1 > row_lo) s[nf][1] = -1e30f;
                if (col > row_lo + 8)     s[nf][2] = -1e30f;
                if (col + 1 > row_lo + 8) s[nf][3] = -1e30f;
            }
        }

        // ---- online softmax ----
        float mx0 = -1e30f, mx1 = -1e30f;
#pragma unroll
        for (int nf = 0; nf < 8; nf++) {
            mx0 = fmaxf(mx0, fmaxf(s[nf][0], s[nf][1]));
            mx1 = fmaxf(mx1, fmaxf(s[nf][2], s[nf][3]));
        }
        mx0 = fmaxf(mx0, __shfl_xor_sync(0xffffffff, mx0, 1));
        mx0 = fmaxf(mx0, __shfl_xor_sync(0xffffffff, mx0, 2));
        mx1 = fmaxf(mx1, __shfl_xor_sync(0xffffffff, mx1, 1));
        mx1 = fmaxf(mx1, __shfl_xor_sync(0xffffffff, mx1, 2));
        float mn0 = fmaxf(m0, mx0), mn1 = fmaxf(m1, mx1);
        float c0 = __expf(m0 - mn0), c1 = __expf(m1 - mn1);
        m0 = mn0; m1 = mn1;

        uint32_t ph[4][4], pl[4][4];
        float sum0 = 0.f, sum1 = 0.f;
#pragma unroll
        for (int nf = 0; nf < 8; nf++) {
            float p0 = __expf(s[nf][0] - mn0);
            float p1 = __expf(s[nf][1] - mn0);
            float p2 = __expf(s[nf][2] - mn1);
            float p3 = __expf(s[nf][3] - mn1);
            sum0 += p0 + p1;
            sum1 += p2 + p3;
            int ks = nf >> 1, rr = (nf & 1) * 2;
            split2(p0, p1, ph[ks][rr], pl[ks][rr]);
            split2(p2, p3, ph[ks][rr + 1], pl[ks][rr + 1]);
        }
        sum0 += __shfl_xor_sync(0xffffffff, sum0, 1);
        sum0 += __shfl_xor_sync(0xffffffff, sum0, 2);
        sum1 += __shfl_xor_sync(0xffffffff, sum1, 1);
        sum1 += __shfl_xor_sync(0xffffffff, sum1, 2);
        l0 = l0 * c0 + sum0;
        l1 = l1 * c1 + sum1;

        // rescale O
#pragma unroll
        for (int nd = 0; nd < 8; nd++) {
            o[nd][0] *= c0; o[nd][1] *= c0;
            o[nd][2] *= c1; o[nd][3] *= c1;
        }

        // ---- O += P V (split 3-MMA) ----
#pragma unroll
        for (int ks = 0; ks < 4; ks++) {
            int kvA = ks * 16 + tg * 2;
            int sw = (g & 3) << 3;
#pragma unroll
            for (int nd = 0; nd < 8; nd++) {
                int d = nd * 8 + g;
                uint32_t u0 = Vhl[d * 64 + (kvA ^ sw)];
                uint32_t u1 = Vhl[d * 64 + ((kvA + 1) ^ sw)];
                uint32_t u2 = Vhl[d * 64 + ((kvA + 8) ^ sw)];
                uint32_t u3 = Vhl[d * 64 + ((kvA + 9) ^ sw)];
                uint32_t vh0 = __byte_perm(u0, u1, 0x5410);
                uint32_t vl0 = __byte_perm(u0, u1, 0x7632);
                uint32_t vh1 = __byte_perm(u2, u3, 0x5410);
                uint32_t vl1 = __byte_perm(u2, u3, 0x7632);
                mma16816(o[nd], ph[ks], vh0, vh1);
                mma16816(o[nd], ph[ks], vl0, vl1);
                mma16816(o[nd], pl[ks], vh0, vh1);
            }
        }
        __syncthreads();
    }

    // ---- epilogue: normalize, split to bf16, write [b*t][h*64+d] ----
    float i0 = 1.f / l0, i1 = 1.f / l1;
#pragma unroll
    for (int nd = 0; nd < 8; nd++) {
        int dcol = h * 64 + nd * 8 + tg * 2;
        {
            size_t off = (size_t)(b * T_ + (row_lo - 0) + q0 * 0 + row_lo - row_lo) ; // placeholder avoidance
        }
        const int grow0 = b * T_ + row_lo;
        const int grow1 = grow0 + 8;
        uint32_t hp, lp;
        split2(o[nd][0] * i0, o[nd][1] * i0, hp, lp);
        *(uint32_t*)(g_ath + (size_t)grow0 * E_ + dcol) = hp;
        *(uint32_t*)(g_atl + (size_t)grow0 * E_ + dcol) = lp;
        split2(o[nd][2] * i1, o[nd][3] * i1, hp, lp);
        *(uint32_t*)(g_ath + (size_t)grow1 * E_ + dcol) = hp;
        *(uint32_t*)(g_atl + (size_t)grow1 * E_ + dcol) = lp;
    }
}

// ---------------------------------------------------------------------------
extern "C" void kernel_launch(void* const* d_in, const int* in_sizes, int n_in,
                              void* d_out, int out_size)
{
    const float* x  = (const float*)d_in[0];
    const float* Wq = (const float*)d_in[1];
    const float* Wk = (const float*)d_in[2];
    const float* Wv = (const float*)d_in[3];
    const float* Wp = (const float*)d_in[4];
    const float* bp = (const float*)d_in[5];
    float* out = (float*)d_out;

    __nv_bfloat16 *xh, *xl, *wph, *wpl;
    cudaGetSymbolAddress((void**)&xh,  g_xh);
    cudaGetSymbolAddress((void**)&xl,  g_xl);
    cudaGetSymbolAddress((void**)&wph, g_wph);
    cudaGetSymbolAddress((void**)&wpl, g_wpl);

    // 1) split-convert x and weights
    conv_split_kernel<<<(M_TOTAL * E_) / 256, 256>>>(x, xh, xl, M_TOTAL * E_);
    conv_wqkv_kernel<<<dim3(E_ / 32, D_ / 32, 3 * H_), 256>>>(Wq, Wk, Wv);
    conv_split_kernel<<<(E_ * E_) / 256, 256>>>(Wp, wph, wpl, E_ * E_);

    // 2) QKV projection -> split-bf16 q/k/v (Q pre-scaled)
    gemm_mma_kernel<<<dim3(M_TOTAL / 128, NQKV / 128), 256>>>(0, nullptr, nullptr);

    // 3) causal flash attention on tensor cores -> g_ath/g_atl
    flash_mma_kernel<<<dim3(T_ / 128, H_, B_), 256>>>();

    // 4) output projection
    gemm_mma_kernel<<<dim3(M_TOTAL / 128, E_ / 128), 256>>>(1, bp, out);
}